// round 1
// baseline (speedup 1.0000x reference)
#include <cuda_runtime.h>
#include <cuda_bf16.h>
#include <math.h>

#define TT 64
#define DD 3136
#define HH 512

// ---------------- scratch (device globals; no allocation allowed) ----------------
__device__ float g_nk[TT*DD], g_nv[TT*DD];
__device__ float g_partKV0[TT*DD], g_partKV1[TT*DD];
__device__ float g_keys[TT*DD], g_vals[TT*DD];
__device__ float g_partA[7][TT*HH];
__device__ float g_a[TT*HH], g_h[TT*HH];
__device__ float g_partY[TT*DD];
__device__ float g_y[TT*DD];
__device__ float g_dY[TT*DD], g_E[TT*DD];
__device__ float g_scp[DD];
__device__ float g_partdH[7][TT*HH];
__device__ float g_dA[TT*HH];
__device__ float g_partG[14][TT*TT];
__device__ float g_Ghat[TT*TT];
__device__ float g_corrA[TT*HH];
__device__ float g_h2[TT*HH];
__device__ float g_partY2[TT*DD];
__device__ float g_partM[4][TT*TT];
__device__ float g_Mhat[TT*TT];
__device__ float g_corrY[TT*DD];
__device__ float g_y2[TT*DD];

// ---------------- helpers ----------------
__device__ __forceinline__ float gelu_f(float x) {
    float u = 0.7978845608028654f * (x + 0.044715f * x * x * x);
    return 0.5f * x * (1.f + tanhf(u));
}
__device__ __forceinline__ float dgelu_f(float x) {
    float x2 = x * x;
    float u = 0.7978845608028654f * (x + 0.044715f * x * x2);
    float th = tanhf(u);
    return 0.5f * (1.f + th)
         + 0.5f * x * (1.f - th * th) * 0.7978845608028654f * (1.f + 3.f * 0.044715f * x2);
}

// block-wide reduce of 3 sums (blockDim.x == 256)
__device__ __forceinline__ void blockReduce3(float& a, float& b, float& c) {
    __shared__ float sb[3][8];
    int lane = threadIdx.x & 31, wid = threadIdx.x >> 5;
    #pragma unroll
    for (int o = 16; o; o >>= 1) {
        a += __shfl_xor_sync(0xffffffffu, a, o);
        b += __shfl_xor_sync(0xffffffffu, b, o);
        c += __shfl_xor_sync(0xffffffffu, c, o);
    }
    if (!lane) { sb[0][wid] = a; sb[1][wid] = b; sb[2][wid] = c; }
    __syncthreads();
    if (threadIdx.x == 0) {
        float x = 0, y = 0, z = 0;
        #pragma unroll
        for (int i = 0; i < 8; i++) { x += sb[0][i]; y += sb[1][i]; z += sb[2][i]; }
        sb[0][0] = x; sb[1][0] = y; sb[2][0] = z;
    }
    __syncthreads();
    a = sb[0][0]; b = sb[1][0]; c = sb[2][0];
}

// ---------------- conv + rmsnorm (k and v in one kernel, x reused from smem) ----------------
__global__ void conv_rms_kernel(const float* __restrict__ x,
                                const float* __restrict__ wk, const float* __restrict__ bk,
                                const float* __restrict__ wv, const float* __restrict__ bv,
                                const float* __restrict__ sck, const float* __restrict__ scv)
{
    int t = blockIdx.x;
    __shared__ float xs[4 * 784];
    __shared__ float wks[144], wvs[144];
    __shared__ float bks[4], bvs[4], scks[4], scvs[4];
    const float* xt = x + t * 3136;
    for (int i = threadIdx.x; i < 3136; i += blockDim.x) xs[i] = xt[i];
    if (threadIdx.x < 144) { wks[threadIdx.x] = wk[threadIdx.x]; wvs[threadIdx.x] = wv[threadIdx.x]; }
    if (threadIdx.x < 4) {
        bks[threadIdx.x] = bk[threadIdx.x]; bvs[threadIdx.x] = bv[threadIdx.x];
        scks[threadIdx.x] = sck[threadIdx.x]; scvs[threadIdx.x] = scv[threadIdx.x];
    }
    __syncthreads();
    for (int p = threadIdx.x; p < 784; p += blockDim.x) {
        int hh = p / 28, ww = p % 28;
        float ak[4], av[4];
        #pragma unroll
        for (int o = 0; o < 4; o++) { ak[o] = bks[o]; av[o] = bvs[o]; }
        #pragma unroll
        for (int kh = 0; kh < 3; kh++) {
            int h2 = hh + kh - 1;
            if (h2 < 0 || h2 >= 28) continue;
            #pragma unroll
            for (int kw = 0; kw < 3; kw++) {
                int w2 = ww + kw - 1;
                if (w2 < 0 || w2 >= 28) continue;
                #pragma unroll
                for (int ci = 0; ci < 4; ci++) {
                    float xv = xs[ci * 784 + h2 * 28 + w2];
                    const float* wkp = &wks[((kh * 3 + kw) * 4 + ci) * 4];
                    const float* wvp = &wvs[((kh * 3 + kw) * 4 + ci) * 4];
                    #pragma unroll
                    for (int o = 0; o < 4; o++) { ak[o] += xv * wkp[o]; av[o] += xv * wvp[o]; }
                }
            }
        }
        float sk = ak[0]*ak[0] + ak[1]*ak[1] + ak[2]*ak[2] + ak[3]*ak[3];
        float sv = av[0]*av[0] + av[1]*av[1] + av[2]*av[2] + av[3]*av[3];
        float invk = rsqrtf(sk * 0.25f + 1e-6f);
        float invv = rsqrtf(sv * 0.25f + 1e-6f);
        float4 ok = make_float4(ak[0]*invk*scks[0], ak[1]*invk*scks[1],
                                ak[2]*invk*scks[2], ak[3]*invk*scks[3]);
        float4 ov = make_float4(av[0]*invv*scvs[0], av[1]*invv*scvs[1],
                                av[2]*invv*scvs[2], av[3]*invv*scvs[3]);
        *reinterpret_cast<float4*>(&g_nk[t * 3136 + p * 4]) = ok;
        *reinterpret_cast<float4*>(&g_nv[t * 3136 + p * 4]) = ov;
    }
}

// ---------------- generic 64-row GEMM: C(64 x N) = A(64 x K) * B ----------------
// tile: 64 rows x 32 cols, K chunks of 32; deterministic split-K into partial buffers
template <bool TRANSB>
__device__ __forceinline__ void gemm_body(const float* __restrict__ A, int lda,
                                          const float* __restrict__ B, int ldb,
                                          float* __restrict__ Cpart, int N,
                                          int kStart, int kChunk, int n0)
{
    const int tid = threadIdx.x;
    const int tx = tid & 31, ty = tid >> 5;
    __shared__ float As[32][65];
    __shared__ float Bs[32][33];
    float acc[8] = {0, 0, 0, 0, 0, 0, 0, 0};
    const int kEnd = kStart + kChunk;
    for (int k0 = kStart; k0 < kEnd; k0 += 32) {
        #pragma unroll
        for (int i = 0; i < 8; i++) {
            int idx = tid + i * 256;
            int r = idx >> 5, kk = idx & 31;
            As[kk][r] = A[r * lda + k0 + kk];
        }
        #pragma unroll
        for (int i = 0; i < 4; i++) {
            int idx = tid + i * 256;
            if (!TRANSB) {
                int kk = idx >> 5, n = idx & 31;
                Bs[kk][n] = B[(size_t)(k0 + kk) * ldb + n0 + n];
            } else {
                int n = idx >> 5, kk = idx & 31;
                Bs[kk][n] = B[(size_t)(n0 + n) * ldb + k0 + kk];
            }
        }
        __syncthreads();
        #pragma unroll
        for (int kk = 0; kk < 32; kk++) {
            float b = Bs[kk][tx];
            #pragma unroll
            for (int r = 0; r < 8; r++) acc[r] += As[kk][ty * 8 + r] * b;
        }
        __syncthreads();
    }
    #pragma unroll
    for (int r = 0; r < 8; r++) Cpart[(ty * 8 + r) * N + n0 + tx] = acc[r];
}

template <bool TRANSB>
__global__ void gemm64(const float* __restrict__ A, int lda,
                       const float* __restrict__ B, int ldb,
                       float* __restrict__ Cpart, int N, int kChunk)
{
    gemm_body<TRANSB>(A, lda, B, ldb, Cpart + (size_t)blockIdx.y * (64 * N), N,
                      blockIdx.y * kChunk, kChunk, blockIdx.x * 32);
}

// both big dense GEMMs (keys & vals) in one launch for full-chip occupancy
__global__ void gemm64_dual(const float* __restrict__ A0, const float* __restrict__ B0, float* C0,
                            const float* __restrict__ A1, const float* __restrict__ B1, float* C1,
                            int N, int K)
{
    if (blockIdx.y == 0) gemm_body<false>(A0, K, B0, N, C0, N, 0, K, blockIdx.x * 32);
    else                 gemm_body<false>(A1, K, B1, N, C1, N, 0, K, blockIdx.x * 32);
}

// ---------------- elementwise / epilogue kernels ----------------
__global__ void add_bias_kernel(float* __restrict__ out, const float* __restrict__ part,
                                const float* __restrict__ bias)
{
    for (int i = blockIdx.x * blockDim.x + threadIdx.x; i < TT * DD; i += gridDim.x * blockDim.x)
        out[i] = part[i] + bias[i % DD];
}

__global__ void ep_ah_kernel(const float* __restrict__ b1)
{
    for (int i = blockIdx.x * blockDim.x + threadIdx.x; i < TT * HH; i += gridDim.x * blockDim.x) {
        float s = b1[i & (HH - 1)];
        #pragma unroll
        for (int p = 0; p < 7; p++) s += g_partA[p][i];
        g_a[i] = s;
        g_h[i] = gelu_f(s);
    }
}

__global__ void k_dY_kernel(const float* __restrict__ sc)
{
    int t = blockIdx.x;
    const float* y = g_y + t * DD;
    const float* v = g_vals + t * DD;
    float S1 = 0, S2 = 0, S3 = 0;
    for (int j = threadIdx.x; j < DD; j += 256) {
        float yj = y[j], scj = sc[j], vj = v[j];
        S1 += yj * yj;
        S2 += scj * scj * yj * yj;
        S3 += vj * scj * yj;
    }
    blockReduce3(S1, S2, S3);
    float inv = rsqrtf(S1 * (1.f / DD) + 1e-6f);
    float s = 2.f * inv * S2 - 2.f * S3;       // sum_j g_j * y_j
    float coef = s * inv * inv * inv * (1.f / DD);
    for (int j = threadIdx.x; j < DD; j += 256) {
        float yj = y[j], scj = sc[j], vj = v[j];
        float pj = yj * inv;
        float e = 2.f * (pj * scj - vj);
        g_dY[t * DD + j] = e * scj * inv - coef * yj;
        g_E[t * DD + j] = e * pj;              // per-token d(loss)/d(scale)
    }
}

__global__ void r_scp_kernel(const float* __restrict__ sc, float c)
{
    int j = blockIdx.x * blockDim.x + threadIdx.x;
    if (j < DD) {
        float s = 0;
        #pragma unroll 8
        for (int t = 0; t < TT; t++) s += g_E[t * DD + j];
        g_scp[j] = sc[j] - c * s;
    }
}

__global__ void ep_dA_kernel()
{
    for (int i = blockIdx.x * blockDim.x + threadIdx.x; i < TT * HH; i += gridDim.x * blockDim.x) {
        float s = 0;
        #pragma unroll
        for (int p = 0; p < 7; p++) s += g_partdH[p][i];
        g_dA[i] = s * dgelu_f(g_a[i]);
    }
}

__global__ void ep_G_kernel()
{
    int i = blockIdx.x * blockDim.x + threadIdx.x;
    if (i < TT * TT) {
        float s = 1.f;   // + 1·1^T folds the b1 gradient into the same correction GEMM
        #pragma unroll
        for (int p = 0; p < 14; p++) s += g_partG[p][i];
        g_Ghat[i] = s;
    }
}

__global__ void ep_h2_kernel(float c)
{
    for (int i = blockIdx.x * blockDim.x + threadIdx.x; i < TT * HH; i += gridDim.x * blockDim.x)
        g_h2[i] = gelu_f(g_a[i] - c * g_corrA[i]);
}

__global__ void ep_M_kernel()
{
    int i = blockIdx.x * blockDim.x + threadIdx.x;
    if (i < TT * TT) {
        float s = 1.f;   // + 1·1^T folds the b2 gradient
        #pragma unroll
        for (int p = 0; p < 4; p++) s += g_partM[p][i];
        g_Mhat[i] = s;
    }
}

__global__ void ep_y2_kernel(const float* __restrict__ b2, float c)
{
    for (int i = blockIdx.x * blockDim.x + threadIdx.x; i < TT * DD; i += gridDim.x * blockDim.x)
        g_y2[i] = g_partY2[i] + b2[i % DD] - c * g_corrY[i];
}

__global__ void k_final_kernel(const float* __restrict__ rmso, float* __restrict__ out)
{
    int t = blockIdx.x;
    const float* y2 = g_y2 + t * DD;
    float S1 = 0, S2 = 0, S3 = 0;
    for (int j = threadIdx.x; j < DD; j += 256) {
        float yj = y2[j];
        float m = yj * g_scp[j];
        S1 += yj * yj;
        S2 += m * m;
    }
    blockReduce3(S1, S2, S3);
    float inv2 = rsqrtf(S1 * (1.f / DD) + 1e-6f);
    float inv3 = rsqrtf(inv2 * inv2 * S2 * (1.f / DD) + 1e-6f);
    float f = inv2 * inv3;
    for (int j = threadIdx.x; j < DD; j += 256)
        out[t * DD + j] = y2[j] * g_scp[j] * f * rmso[j];
}

// ---------------- host launch ----------------
extern "C" void kernel_launch(void* const* d_in, const int* in_sizes, int n_in,
                              void* d_out, int out_size)
{
    const float* x        = (const float*)d_in[0];
    const float* conv_k_w = (const float*)d_in[1];
    const float* conv_k_b = (const float*)d_in[2];
    const float* conv_v_w = (const float*)d_in[3];
    const float* conv_v_b = (const float*)d_in[4];
    const float* rms_k_sc = (const float*)d_in[5];
    const float* rms_v_sc = (const float*)d_in[6];
    const float* dense_k_w = (const float*)d_in[7];
    const float* dense_k_b = (const float*)d_in[8];
    const float* dense_v_w = (const float*)d_in[9];
    const float* dense_v_b = (const float*)d_in[10];
    const float* mem_w1 = (const float*)d_in[11];
    const float* mem_b1 = (const float*)d_in[12];
    const float* mem_w2 = (const float*)d_in[13];
    const float* mem_b2 = (const float*)d_in[14];
    const float* mem_sc = (const float*)d_in[15];
    const float* rms_out_sc = (const float*)d_in[16];
    float* out = (float*)d_out;

    // weights_t = etas_t * betas[-1]/betas_t = 0.1 * 0.9^63 (constant in t); agg scale 1e-4
    double wconst = 0.1 * pow(0.9, 63.0);
    float c = (float)(1e-4 * wconst);

    float *nkP, *nvP, *keysP, *valsP, *partKV0P, *partKV1P;
    float *partAP, *partYP, *partdHP, *partGP, *corrAP, *partY2P, *partMP, *corrYP;
    float *hP, *dYP, *GhatP, *h2P, *MhatP, *dAP;
    cudaGetSymbolAddress((void**)&nkP, g_nk);
    cudaGetSymbolAddress((void**)&nvP, g_nv);
    cudaGetSymbolAddress((void**)&partKV0P, g_partKV0);
    cudaGetSymbolAddress((void**)&partKV1P, g_partKV1);
    cudaGetSymbolAddress((void**)&keysP, g_keys);
    cudaGetSymbolAddress((void**)&valsP, g_vals);
    cudaGetSymbolAddress((void**)&partAP, g_partA);
    cudaGetSymbolAddress((void**)&hP, g_h);
    cudaGetSymbolAddress((void**)&partYP, g_partY);
    cudaGetSymbolAddress((void**)&dYP, g_dY);
    cudaGetSymbolAddress((void**)&partdHP, g_partdH);
    cudaGetSymbolAddress((void**)&partGP, g_partG);
    cudaGetSymbolAddress((void**)&GhatP, g_Ghat);
    cudaGetSymbolAddress((void**)&dAP, g_dA);
    cudaGetSymbolAddress((void**)&corrAP, g_corrA);
    cudaGetSymbolAddress((void**)&h2P, g_h2);
    cudaGetSymbolAddress((void**)&partY2P, g_partY2);
    cudaGetSymbolAddress((void**)&partMP, g_partM);
    cudaGetSymbolAddress((void**)&MhatP, g_Mhat);
    cudaGetSymbolAddress((void**)&corrYP, g_corrY);
    float* yP;       cudaGetSymbolAddress((void**)&yP, g_y);

    // 1. conv + per-pixel rmsnorm -> nk, nv
    conv_rms_kernel<<<TT, 256>>>(x, conv_k_w, conv_k_b, conv_v_w, conv_v_b, rms_k_sc, rms_v_sc);

    // 2. keys/vals = nk/nv @ W (64x3136x3136, both in one launch)
    gemm64_dual<<<dim3(98, 2), 256>>>(nkP, dense_k_w, partKV0P,
                                      nvP, dense_v_w, partKV1P, DD, DD);
    add_bias_kernel<<<392, 256>>>(keysP, partKV0P, dense_k_b);
    add_bias_kernel<<<392, 256>>>(valsP, partKV1P, dense_v_b);

    // 3. a = keys @ w1 + b1 ; h = gelu(a)
    gemm64<false><<<dim3(16, 7), 256>>>(keysP, DD, mem_w1, HH, partAP, HH, 448);
    ep_ah_kernel<<<128, 256>>>(mem_b1);

    // 4. y = h @ w2 + b2
    gemm64<false><<<dim3(98, 1), 256>>>(hP, HH, mem_w2, DD, partYP, DD, HH);
    add_bias_kernel<<<392, 256>>>(yP, partYP, mem_b2);

    // 5. per-token rmsnorm-backward -> dY, E(scale-grad)
    k_dY_kernel<<<TT, 256>>>(mem_sc);
    r_scp_kernel<<<13, 256>>>(mem_sc, c);

    // 6. dH = dY @ w2^T ; dA = dH * gelu'(a)
    gemm64<true><<<dim3(16, 7), 256>>>(dYP, DD, mem_w2, DD, partdHP, HH, 448);
    ep_dA_kernel<<<128, 256>>>();

    // 7. Ghat = K K^T + 1 ; corrA = Ghat @ dA ; h2 = gelu(a - c*corrA)
    gemm64<true><<<dim3(2, 14), 256>>>(keysP, DD, keysP, DD, partGP, TT, 224);
    ep_G_kernel<<<16, 256>>>();
    gemm64<false><<<dim3(16, 1), 256>>>(GhatP, TT, dAP, HH, corrAP, HH, TT);
    ep_h2_kernel<<<128, 256>>>(c);

    // 8. y2 = h2 @ w2 + b2 - c*(h2 H^T + 1) @ dY
    gemm64<false><<<dim3(98, 1), 256>>>(h2P, HH, mem_w2, DD, partY2P, DD, HH);
    gemm64<true><<<dim3(2, 4), 256>>>(h2P, HH, hP, HH, partMP, TT, 128);
    ep_M_kernel<<<16, 256>>>();
    gemm64<false><<<dim3(98, 1), 256>>>(MhatP, TT, dYP, DD, corrYP, DD, TT);
    ep_y2_kernel<<<392, 256>>>(mem_b2, c);

    // 9. out = rmsnorm(rmsnorm(y2)*sc', rms_out_scale)
    k_final_kernel<<<TT, 256>>>(rms_out_sc, out);

    (void)in_sizes; (void)n_in; (void)out_size;
}

// round 3
// speedup vs baseline: 2.1054x; 2.1054x over previous
#include <cuda_runtime.h>
#include <cuda_bf16.h>
#include <math.h>

#define TT 64
#define DD 3136
#define HH 512

// ---------------- scratch (device globals; no allocation allowed) ----------------
__device__ __align__(16) float g_nk[TT*DD], g_nv[TT*DD];
__device__ __align__(16) float g_partKV0[3][TT*DD], g_partKV1[3][TT*DD];
__device__ __align__(16) float g_keys[TT*DD], g_vals[TT*DD];
__device__ __align__(16) float g_partA[7][TT*HH];
__device__ __align__(16) float g_a[TT*HH], g_h[TT*HH];
__device__ __align__(16) float g_partY[2][TT*DD];
__device__ __align__(16) float g_y[TT*DD];
__device__ __align__(16) float g_dY[TT*DD], g_E[TT*DD];
__device__ __align__(16) float g_scp[DD];
__device__ __align__(16) float g_partdH[7][TT*HH];
__device__ __align__(16) float g_dA[TT*HH];
__device__ __align__(16) float g_partG[14][TT*TT];
__device__ __align__(16) float g_Ghat[TT*TT];
__device__ __align__(16) float g_corrA[TT*HH];
__device__ __align__(16) float g_h2[TT*HH];
__device__ __align__(16) float g_partY2[2][TT*DD];
__device__ __align__(16) float g_partM[4][TT*TT];
__device__ __align__(16) float g_Mhat[TT*TT];
__device__ __align__(16) float g_corrY[TT*DD];
__device__ __align__(16) float g_y2[TT*DD];

// ---------------- helpers ----------------
__device__ __forceinline__ float gelu_f(float x) {
    float u = 0.7978845608028654f * (x + 0.044715f * x * x * x);
    return 0.5f * x * (1.f + tanhf(u));
}
__device__ __forceinline__ float dgelu_f(float x) {
    float x2 = x * x;
    float u = 0.7978845608028654f * (x + 0.044715f * x * x2);
    float th = tanhf(u);
    return 0.5f * (1.f + th)
         + 0.5f * x * (1.f - th * th) * 0.7978845608028654f * (1.f + 3.f * 0.044715f * x2);
}

__device__ __forceinline__ float f2tf(float x) {
    unsigned u;
    asm("cvt.rna.tf32.f32 %0, %1;" : "=r"(u) : "f"(x));
    return __uint_as_float(u);
}

__device__ __forceinline__ void mma8(float* c, const unsigned* a, unsigned b0, unsigned b1) {
    asm volatile("mma.sync.aligned.m16n8k8.row.col.f32.tf32.tf32.f32 "
        "{%0,%1,%2,%3}, {%4,%5,%6,%7}, {%8,%9}, {%0,%1,%2,%3};\n"
        : "+f"(c[0]), "+f"(c[1]), "+f"(c[2]), "+f"(c[3])
        : "r"(a[0]), "r"(a[1]), "r"(a[2]), "r"(a[3]), "r"(b0), "r"(b1));
}

// block-wide reduce of 3 sums (blockDim.x == 256)
__device__ __forceinline__ void blockReduce3(float& a, float& b, float& c) {
    __shared__ float sb[3][8];
    int lane = threadIdx.x & 31, wid = threadIdx.x >> 5;
    #pragma unroll
    for (int o = 16; o; o >>= 1) {
        a += __shfl_xor_sync(0xffffffffu, a, o);
        b += __shfl_xor_sync(0xffffffffu, b, o);
        c += __shfl_xor_sync(0xffffffffu, c, o);
    }
    if (!lane) { sb[0][wid] = a; sb[1][wid] = b; sb[2][wid] = c; }
    __syncthreads();
    if (threadIdx.x == 0) {
        float x = 0, y = 0, z = 0;
        #pragma unroll
        for (int i = 0; i < 8; i++) { x += sb[0][i]; y += sb[1][i]; z += sb[2][i]; }
        sb[0][0] = x; sb[1][0] = y; sb[2][0] = z;
    }
    __syncthreads();
    a = sb[0][0]; b = sb[1][0]; c = sb[2][0];
}

// ---------------- conv + rmsnorm (k and v in one kernel, x reused from smem) ----------------
__global__ void conv_rms_kernel(const float* __restrict__ x,
                                const float* __restrict__ wk, const float* __restrict__ bk,
                                const float* __restrict__ wv, const float* __restrict__ bv,
                                const float* __restrict__ sck, const float* __restrict__ scv)
{
    int t = blockIdx.x;
    __shared__ float xs[4 * 784];
    __shared__ float wks[144], wvs[144];
    __shared__ float bks[4], bvs[4], scks[4], scvs[4];
    const float* xt = x + t * 3136;
    for (int i = threadIdx.x; i < 3136; i += blockDim.x) xs[i] = xt[i];
    if (threadIdx.x < 144) { wks[threadIdx.x] = wk[threadIdx.x]; wvs[threadIdx.x] = wv[threadIdx.x]; }
    if (threadIdx.x < 4) {
        bks[threadIdx.x] = bk[threadIdx.x]; bvs[threadIdx.x] = bv[threadIdx.x];
        scks[threadIdx.x] = sck[threadIdx.x]; scvs[threadIdx.x] = scv[threadIdx.x];
    }
    __syncthreads();
    for (int p = threadIdx.x; p < 784; p += blockDim.x) {
        int hh = p / 28, ww = p % 28;
        float ak[4], av[4];
        #pragma unroll
        for (int o = 0; o < 4; o++) { ak[o] = bks[o]; av[o] = bvs[o]; }
        #pragma unroll
        for (int kh = 0; kh < 3; kh++) {
            int h2 = hh + kh - 1;
            if (h2 < 0 || h2 >= 28) continue;
            #pragma unroll
            for (int kw = 0; kw < 3; kw++) {
                int w2 = ww + kw - 1;
                if (w2 < 0 || w2 >= 28) continue;
                #pragma unroll
                for (int ci = 0; ci < 4; ci++) {
                    float xv = xs[ci * 784 + h2 * 28 + w2];
                    const float* wkp = &wks[((kh * 3 + kw) * 4 + ci) * 4];
                    const float* wvp = &wvs[((kh * 3 + kw) * 4 + ci) * 4];
                    #pragma unroll
                    for (int o = 0; o < 4; o++) { ak[o] += xv * wkp[o]; av[o] += xv * wvp[o]; }
                }
            }
        }
        float sk = ak[0]*ak[0] + ak[1]*ak[1] + ak[2]*ak[2] + ak[3]*ak[3];
        float sv = av[0]*av[0] + av[1]*av[1] + av[2]*av[2] + av[3]*av[3];
        float invk = rsqrtf(sk * 0.25f + 1e-6f);
        float invv = rsqrtf(sv * 0.25f + 1e-6f);
        float4 ok = make_float4(ak[0]*invk*scks[0], ak[1]*invk*scks[1],
                                ak[2]*invk*scks[2], ak[3]*invk*scks[3]);
        float4 ov = make_float4(av[0]*invv*scvs[0], av[1]*invv*scvs[1],
                                av[2]*invv*scvs[2], av[3]*invv*scvs[3]);
        *reinterpret_cast<float4*>(&g_nk[t * 3136 + p * 4]) = ok;
        *reinterpret_cast<float4*>(&g_nv[t * 3136 + p * 4]) = ov;
    }
}

// ---------------- tensor-core tf32 GEMM: C(64 x N) = A(64 x K) * B ----------------
// block = 256 threads (8 warps), tile 64(M) x 64(N), K-chunks of 32.
// warp (w&3) -> M row 16*(w&3);  (w>>2) -> N col 32*(w>>2); per warp 4x4 m16n8k8 MMAs/chunk.
// A smem stride 36: fragment reads bank (4g+t) conflict-free, float4 stores conflict-free.
// B smem stride 72 (non-trans: all conflict-free) / 73 (trans: scatter-store conflict-free).
template <bool TRANSB>
__device__ __forceinline__ void gemm_tc_body(
    const float* __restrict__ A, int lda,
    const float* __restrict__ B, int ldb,
    float* __restrict__ Cp, int N,
    int kStart, int kEnd, int n0)
{
    constexpr int BS = TRANSB ? 73 : 72;
    __shared__ float As[64 * 36];
    __shared__ float Bs[32 * BS];
    const int tid = threadIdx.x;
    const int lane = tid & 31, wid = tid >> 5;
    const int mrow = (wid & 3) * 16;
    const int ncol = (wid >> 2) * 32;
    const int g = lane >> 2, t = lane & 3;
    float acc[4][4] = {};

    for (int k0 = kStart; k0 < kEnd; k0 += 32) {
        // A tile 64x32
        #pragma unroll
        for (int i = 0; i < 2; i++) {
            int j = tid + i * 256;
            int r = j >> 3, k4 = (j & 7) * 4;
            float4 v = *reinterpret_cast<const float4*>(A + (size_t)r * lda + k0 + k4);
            float4 w;
            w.x = f2tf(v.x); w.y = f2tf(v.y); w.z = f2tf(v.z); w.w = f2tf(v.w);
            *reinterpret_cast<float4*>(&As[r * 36 + k4]) = w;
        }
        // B tile 32x64 (Bs[k][n])
        if (!TRANSB) {
            #pragma unroll
            for (int i = 0; i < 2; i++) {
                int j = tid + i * 256;
                int r = j >> 4, n4 = (j & 15) * 4;
                float4 v = *reinterpret_cast<const float4*>(B + (size_t)(k0 + r) * ldb + n0 + n4);
                float4 w;
                w.x = f2tf(v.x); w.y = f2tf(v.y); w.z = f2tf(v.z); w.w = f2tf(v.w);
                *reinterpret_cast<float4*>(&Bs[r * BS + n4]) = w;
            }
        } else {
            #pragma unroll
            for (int i = 0; i < 2; i++) {
                int j = tid + i * 256;
                int nr = j >> 3, k4 = (j & 7) * 4;
                float4 v = *reinterpret_cast<const float4*>(B + (size_t)(n0 + nr) * ldb + k0 + k4);
                Bs[(k4 + 0) * BS + nr] = f2tf(v.x);
                Bs[(k4 + 1) * BS + nr] = f2tf(v.y);
                Bs[(k4 + 2) * BS + nr] = f2tf(v.z);
                Bs[(k4 + 3) * BS + nr] = f2tf(v.w);
            }
        }
        __syncthreads();

        unsigned a[4][4];
        #pragma unroll
        for (int kt = 0; kt < 4; kt++) {
            int kb = kt * 8;
            a[kt][0] = __float_as_uint(As[(mrow + g) * 36 + kb + t]);
            a[kt][1] = __float_as_uint(As[(mrow + g + 8) * 36 + kb + t]);
            a[kt][2] = __float_as_uint(As[(mrow + g) * 36 + kb + t + 4]);
            a[kt][3] = __float_as_uint(As[(mrow + g + 8) * 36 + kb + t + 4]);
        }
        #pragma unroll
        for (int kt = 0; kt < 4; kt++) {
            #pragma unroll
            for (int nt = 0; nt < 4; nt++) {
                unsigned b0 = __float_as_uint(Bs[(kt * 8 + t) * BS + ncol + nt * 8 + g]);
                unsigned b1 = __float_as_uint(Bs[(kt * 8 + t + 4) * BS + ncol + nt * 8 + g]);
                mma8(acc[nt], a[kt], b0, b1);
            }
        }
        __syncthreads();
    }

    #pragma unroll
    for (int nt = 0; nt < 4; nt++) {
        int col = n0 + ncol + nt * 8 + t * 2;
        Cp[(size_t)(mrow + g) * N + col]         = acc[nt][0];
        Cp[(size_t)(mrow + g) * N + col + 1]     = acc[nt][1];
        Cp[(size_t)(mrow + g + 8) * N + col]     = acc[nt][2];
        Cp[(size_t)(mrow + g + 8) * N + col + 1] = acc[nt][3];
    }
}

template <bool TRANSB>
__global__ void gemm_tc(const float* __restrict__ A, int lda,
                        const float* __restrict__ B, int ldb,
                        float* __restrict__ Cpart, int N,
                        int kChunk, int Ktot)
{
    int kStart = blockIdx.y * kChunk;
    int kEnd = kStart + kChunk; if (kEnd > Ktot) kEnd = Ktot;
    gemm_tc_body<TRANSB>(A, lda, B, ldb,
                         Cpart + (size_t)blockIdx.y * (64 * N), N,
                         kStart, kEnd, blockIdx.x * 64);
}

// both big dense GEMMs in one launch (z selects matrix)
__global__ void gemm_dual_tc(const float* __restrict__ A0, const float* __restrict__ B0, float* C0,
                             const float* __restrict__ A1, const float* __restrict__ B1, float* C1,
                             int N, int kChunk, int Ktot)
{
    const float* A = blockIdx.z ? A1 : A0;
    const float* B = blockIdx.z ? B1 : B0;
    float* C = blockIdx.z ? C1 : C0;
    int kStart = blockIdx.y * kChunk;
    int kEnd = kStart + kChunk; if (kEnd > Ktot) kEnd = Ktot;
    gemm_tc_body<false>(A, Ktot, B, N, C + (size_t)blockIdx.y * (64 * N), N,
                        kStart, kEnd, blockIdx.x * 64);
}

// ---------------- elementwise / epilogue kernels ----------------
__global__ void ep_sum_bias(float* __restrict__ out, const float* __restrict__ part,
                            const float* __restrict__ bias, int P)
{
    for (int i = blockIdx.x * blockDim.x + threadIdx.x; i < TT * DD; i += gridDim.x * blockDim.x) {
        float s = bias[i % DD];
        for (int p = 0; p < P; p++) s += part[(size_t)p * (TT * DD) + i];
        out[i] = s;
    }
}

__global__ void ep_ah_kernel(const float* __restrict__ b1)
{
    for (int i = blockIdx.x * blockDim.x + threadIdx.x; i < TT * HH; i += gridDim.x * blockDim.x) {
        float s = b1[i & (HH - 1)];
        #pragma unroll
        for (int p = 0; p < 7; p++) s += g_partA[p][i];
        g_a[i] = s;
        g_h[i] = gelu_f(s);
    }
}

__global__ void k_dY_kernel(const float* __restrict__ sc)
{
    int t = blockIdx.x;
    const float* y = g_y + t * DD;
    const float* v = g_vals + t * DD;
    float S1 = 0, S2 = 0, S3 = 0;
    for (int j = threadIdx.x; j < DD; j += 256) {
        float yj = y[j], scj = sc[j], vj = v[j];
        S1 += yj * yj;
        S2 += scj * scj * yj * yj;
        S3 += vj * scj * yj;
    }
    blockReduce3(S1, S2, S3);
    float inv = rsqrtf(S1 * (1.f / DD) + 1e-6f);
    float s = 2.f * inv * S2 - 2.f * S3;       // sum_j g_j * y_j
    float coef = s * inv * inv * inv * (1.f / DD);
    for (int j = threadIdx.x; j < DD; j += 256) {
        float yj = y[j], scj = sc[j], vj = v[j];
        float pj = yj * inv;
        float e = 2.f * (pj * scj - vj);
        g_dY[t * DD + j] = e * scj * inv - coef * yj;
        g_E[t * DD + j] = e * pj;              // per-token d(loss)/d(scale)
    }
}

__global__ void r_scp_kernel(const float* __restrict__ sc, float c)
{
    int j = blockIdx.x * blockDim.x + threadIdx.x;
    if (j < DD) {
        float s = 0;
        #pragma unroll 8
        for (int t = 0; t < TT; t++) s += g_E[t * DD + j];
        g_scp[j] = sc[j] - c * s;
    }
}

__global__ void ep_dA_kernel()
{
    for (int i = blockIdx.x * blockDim.x + threadIdx.x; i < TT * HH; i += gridDim.x * blockDim.x) {
        float s = 0;
        #pragma unroll
        for (int p = 0; p < 7; p++) s += g_partdH[p][i];
        g_dA[i] = s * dgelu_f(g_a[i]);
    }
}

__global__ void ep_G_kernel()
{
    int i = blockIdx.x * blockDim.x + threadIdx.x;
    if (i < TT * TT) {
        float s = 1.f;   // + 1·1^T folds the b1 gradient into the same correction GEMM
        #pragma unroll
        for (int p = 0; p < 14; p++) s += g_partG[p][i];
        g_Ghat[i] = s;
    }
}

__global__ void ep_h2_kernel(float c)
{
    for (int i = blockIdx.x * blockDim.x + threadIdx.x; i < TT * HH; i += gridDim.x * blockDim.x)
        g_h2[i] = gelu_f(g_a[i] - c * g_corrA[i]);
}

__global__ void ep_M_kernel()
{
    int i = blockIdx.x * blockDim.x + threadIdx.x;
    if (i < TT * TT) {
        float s = 1.f;   // + 1·1^T folds the b2 gradient
        #pragma unroll
        for (int p = 0; p < 4; p++) s += g_partM[p][i];
        g_Mhat[i] = s;
    }
}

__global__ void ep_y2_kernel(const float* __restrict__ b2, float c)
{
    for (int i = blockIdx.x * blockDim.x + threadIdx.x; i < TT * DD; i += gridDim.x * blockDim.x)
        g_y2[i] = g_partY2[0][i] + g_partY2[1][i] + b2[i % DD] - c * g_corrY[i];
}

__global__ void k_final_kernel(const float* __restrict__ rmso, float* __restrict__ out)
{
    int t = blockIdx.x;
    const float* y2 = g_y2 + t * DD;
    float S1 = 0, S2 = 0, S3 = 0;
    for (int j = threadIdx.x; j < DD; j += 256) {
        float yj = y2[j];
        float m = yj * g_scp[j];
        S1 += yj * yj;
        S2 += m * m;
    }
    blockReduce3(S1, S2, S3);
    float inv2 = rsqrtf(S1 * (1.f / DD) + 1e-6f);
    float inv3 = rsqrtf(inv2 * inv2 * S2 * (1.f / DD) + 1e-6f);
    float f = inv2 * inv3;
    for (int j = threadIdx.x; j < DD; j += 256)
        out[t * DD + j] = y2[j] * g_scp[j] * f * rmso[j];
}

// ---------------- host launch ----------------
extern "C" void kernel_launch(void* const* d_in, const int* in_sizes, int n_in,
                              void* d_out, int out_size)
{
    const float* x        = (const float*)d_in[0];
    const float* conv_k_w = (const float*)d_in[1];
    const float* conv_k_b = (const float*)d_in[2];
    const float* conv_v_w = (const float*)d_in[3];
    const float* conv_v_b = (const float*)d_in[4];
    const float* rms_k_sc = (const float*)d_in[5];
    const float* rms_v_sc = (const float*)d_in[6];
    const float* dense_k_w = (const float*)d_in[7];
    const float* dense_k_b = (const float*)d_in[8];
    const float* dense_v_w = (const float*)d_in[9];
    const float* dense_v_b = (const float*)d_in[10];
    const float* mem_w1 = (const float*)d_in[11];
    const float* mem_b1 = (const float*)d_in[12];
    const float* mem_w2 = (const float*)d_in[13];
    const float* mem_b2 = (const float*)d_in[14];
    const float* mem_sc = (const float*)d_in[15];
    const float* rms_out_sc = (const float*)d_in[16];
    float* out = (float*)d_out;

    // weights_t = etas_t * betas[-1]/betas_t = 0.1 * 0.9^63 (constant in t); agg scale 1e-4
    double wconst = 0.1 * pow(0.9, 63.0);
    float c = (float)(1e-4 * wconst);

    float *nkP, *nvP, *keysP, *valsP, *partKV0P, *partKV1P;
    float *partAP, *partYP, *partdHP, *partGP, *corrAP, *partY2P, *partMP, *corrYP;
    float *hP, *dYP, *GhatP, *h2P, *MhatP, *dAP, *yP;
    cudaGetSymbolAddress((void**)&nkP, g_nk);
    cudaGetSymbolAddress((void**)&nvP, g_nv);
    cudaGetSymbolAddress((void**)&partKV0P, g_partKV0);
    cudaGetSymbolAddress((void**)&partKV1P, g_partKV1);
    cudaGetSymbolAddress((void**)&keysP, g_keys);
    cudaGetSymbolAddress((void**)&valsP, g_vals);
    cudaGetSymbolAddress((void**)&partAP, g_partA);
    cudaGetSymbolAddress((void**)&hP, g_h);
    cudaGetSymbolAddress((void**)&partYP, g_partY);
    cudaGetSymbolAddress((void**)&dYP, g_dY);
    cudaGetSymbolAddress((void**)&partdHP, g_partdH);
    cudaGetSymbolAddress((void**)&partGP, g_partG);
    cudaGetSymbolAddress((void**)&GhatP, g_Ghat);
    cudaGetSymbolAddress((void**)&dAP, g_dA);
    cudaGetSymbolAddress((void**)&corrAP, g_corrA);
    cudaGetSymbolAddress((void**)&h2P, g_h2);
    cudaGetSymbolAddress((void**)&partY2P, g_partY2);
    cudaGetSymbolAddress((void**)&partMP, g_partM);
    cudaGetSymbolAddress((void**)&MhatP, g_Mhat);
    cudaGetSymbolAddress((void**)&corrYP, g_corrY);
    cudaGetSymbolAddress((void**)&yP, g_y);

    // 1. conv + per-pixel rmsnorm -> nk, nv
    conv_rms_kernel<<<TT, 256>>>(x, conv_k_w, conv_k_b, conv_v_w, conv_v_b, rms_k_sc, rms_v_sc);

    // 2. keys/vals = nk/nv @ W (64x3136x3136, both in one launch; splitK=3)
    gemm_dual_tc<<<dim3(49, 3, 2), 256>>>(nkP, dense_k_w, partKV0P,
                                          nvP, dense_v_w, partKV1P, DD, 1056, DD);
    ep_sum_bias<<<392, 256>>>(keysP, partKV0P, dense_k_b, 3);
    ep_sum_bias<<<392, 256>>>(valsP, partKV1P, dense_v_b, 3);

    // 3. a = keys @ w1 + b1 ; h = gelu(a)
    gemm_tc<false><<<dim3(8, 7), 256>>>(keysP, DD, mem_w1, HH, partAP, HH, 448, DD);
    ep_ah_kernel<<<128, 256>>>(mem_b1);

    // 4. y = h @ w2 + b2
    gemm_tc<false><<<dim3(49, 2), 256>>>(hP, HH, mem_w2, DD, partYP, DD, 256, HH);
    ep_sum_bias<<<392, 256>>>(yP, partYP, mem_b2, 2);

    // 5. per-token rmsnorm-backward -> dY, E(scale-grad)
    k_dY_kernel<<<TT, 256>>>(mem_sc);
    r_scp_kernel<<<13, 256>>>(mem_sc, c);

    // 6. dH = dY @ w2^T ; dA = dH * gelu'(a)
    gemm_tc<true><<<dim3(8, 7), 256>>>(dYP, DD, mem_w2, DD, partdHP, HH, 448, DD);
    ep_dA_kernel<<<128, 256>>>();

    // 7. Ghat = K K^T + 1 ; corrA = Ghat @ dA ; h2 = gelu(a - c*corrA)
    gemm_tc<true><<<dim3(1, 14), 256>>>(keysP, DD, keysP, DD, partGP, TT, 224, DD);
    ep_G_kernel<<<16, 256>>>();
    gemm_tc<false><<<dim3(8, 1), 256>>>(GhatP, TT, dAP, HH, corrAP, HH, 64, TT);
    ep_h2_kernel<<<128, 256>>>(c);

    // 8. y2 = h2 @ w2 + b2 - c*(h2 H^T + 1) @ dY
    gemm_tc<false><<<dim3(49, 2), 256>>>(h2P, HH, mem_w2, DD, partY2P, DD, 256, HH);
    gemm_tc<true><<<dim3(1, 4), 256>>>(h2P, HH, hP, HH, partMP, TT, 128, HH);
    ep_M_kernel<<<16, 256>>>();
    gemm_tc<false><<<dim3(49, 1), 256>>>(MhatP, TT, dYP, DD, corrYP, DD, 64, TT);
    ep_y2_kernel<<<392, 256>>>(mem_b2, c);

    // 9. out = rmsnorm(rmsnorm(y2)*sc', rms_out_scale)
    k_final_kernel<<<TT, 256>>>(rms_out_sc, out);

    (void)in_sizes; (void)n_in; (void)out_size;
}